// round 12
// baseline (speedup 1.0000x reference)
#include <cuda_runtime.h>
#include <stdint.h>

#define IN_W 256
#define IN_HW 65536
#define OUT_W 254
#define OUT_HW (254 * 254)

#define PITCH 68                 // words per staged row (64 + 2 halo + 2 pad)
#define PLANE 408                // 6*PITCH; %32==24 -> k*PLANE banks {0,24,16,8}: conflict-free
#define BUFW (8 * PLANE)         // 3264 words per stage (8 ci-planes)
#define BF_WORDS 2304            // 18 ksteps * 32 lanes * 4 words (lane-ordered W fragments)
#define SMEM_BYTES ((3 * BUFW + BF_WORDS + 16) * 4)   // 48,448 B -> 3 CTAs/SM

__device__ __forceinline__ uint32_t tf32r(float f) {
    uint32_t r; asm("cvt.rna.tf32.f32 %0, %1;" : "=r"(r) : "f"(f)); return r;
}
// D(m16=co, n8=pos) += A(weights) * B(inputs)
__device__ __forceinline__ void mma_tf32(float c[4], uint32_t a0, uint32_t a1,
                                         uint32_t a2, uint32_t a3,
                                         uint32_t b0, uint32_t b1) {
    asm("mma.sync.aligned.m16n8k8.row.col.f32.tf32.tf32.f32 "
        "{%0,%1,%2,%3}, {%4,%5,%6,%7}, {%8,%9}, {%0,%1,%2,%3};"
        : "+f"(c[0]), "+f"(c[1]), "+f"(c[2]), "+f"(c[3])
        : "r"(a0), "r"(a1), "r"(a2), "r"(a3), "r"(b0), "r"(b1));
}
__device__ __forceinline__ float mish_f(float v) {
    if (v > 30.0f) return v;
    float e  = __expf(v);
    float t  = 1.0f + e;
    float t2 = t * t;
    return v * __fdividef(t2 - 1.0f, t2 + 1.0f);
}

__global__ __launch_bounds__(256, 3)
void conv_tc_kernel(const float* __restrict__ x,
                    const float* __restrict__ w,
                    const float* __restrict__ bias,
                    float* __restrict__ y)
{
    extern __shared__ uint32_t sm[];
    uint32_t* stage = sm;                    // 3 half-K stage buffers [ci8][row6][pos68]
    uint32_t* Wf    = sm + 3 * BUFW;         // lane-ordered weight A-fragments (uint4/lane)
    float*    bsm   = (float*)(sm + 3 * BUFW + BF_WORDS);

    const int tid  = threadIdx.x;
    const int wid  = tid >> 5;
    const int lane = tid & 31;
    const int lm   = lane >> 2;              // C row group / B col (pos)
    const int lk   = lane & 3;               // C col group / B k
    const int X0   = blockIdx.x * 64;
    const int Y0   = blockIdx.y * 16;
    const int n    = blockIdx.z;

    if (tid < 16) bsm[tid] = bias[tid];

    // ---- W A-fragments: Wf[(kc*9+ky*3+kx)*128 + lane*4 + word]
    // word0:(co=lane>>2, ci_h=lane&3) word1:(co+8,ci_h) word2:(co,ci_h+4) word3:(co+8,ci_h+4)
    for (int i = tid; i < BF_WORDS; i += 256) {
        int word = i & 3;
        int ln   = (i >> 2) & 31;
        int t    = i >> 7;                   // kc*9 + ky*3 + kx
        int kx   = t % 3;
        int kyc  = t / 3;
        int ky   = kyc % 3;
        int kc   = kyc / 3;
        int co   = (ln >> 2) + (word & 1) * 8;
        int ci   = kc * 8 + (ln & 3) + (word >> 1) * 4;
        Wf[t * 128 + ln * 4 + word] = tf32r(w[(co * 16 + ci) * 9 + ky * 3 + kx]);
    }

    const float* xn = x + (size_t)n * 16 * IN_HW;
    const uint32_t sb = (uint32_t)__cvta_generic_to_shared(stage);

    // ---- precomputed loader slots: 768 body chunks = 3/thread, 48 halo (tid<48)
    int      srow[3];
    uint32_t soff[3];
    uint32_t sdst[3];
    #pragma unroll
    for (int s = 0; s < 3; s++) {
        int j     = tid + 256 * s;
        int pos16 = j & 15;
        int rc    = j >> 4;
        int row   = rc % 6;
        int cil   = rc / 6;
        srow[s] = row;
        soff[s] = (uint32_t)(cil * IN_HW + X0 + pos16 * 4);
        sdst[s] = (uint32_t)((cil * PLANE + row * PITCH + pos16 * 4) * 4);
    }
    int hrow = 0; uint32_t hoff = 0, hdst = 0;
    if (tid < 48) {
        int cil = tid / 6;
        hrow = tid % 6;
        int gx = X0 + 64; if (gx > 252) gx = 252;   // dummy: guarded outputs only
        hoff = (uint32_t)(cil * IN_HW + gx);
        hdst = (uint32_t)((cil * PLANE + hrow * PITCH + 64) * 4);
    }

    #define LOAD_PH(p, ph)                                                          \
    do {                                                                            \
        int Ys = Y0 + 4 * ((ph) >> 1);                                              \
        uint32_t cofs = ((ph) & 1) ? (uint32_t)(8 * IN_HW) : 0u;                    \
        uint32_t sbp  = sb + (uint32_t)(p) * (BUFW * 4);                            \
        _Pragma("unroll")                                                           \
        for (int s = 0; s < 3; s++) {                                               \
            int gy = Ys + srow[s]; if (gy > 255) gy = 255;                          \
            const float* src = xn + cofs + soff[s] + gy * IN_W;                     \
            asm volatile("cp.async.cg.shared.global [%0], [%1], 16;"                \
                         :: "r"(sbp + sdst[s]), "l"(src));                          \
        }                                                                           \
        if (tid < 48) {                                                             \
            int gy = Ys + hrow; if (gy > 255) gy = 255;                             \
            const float* src = xn + cofs + hoff + gy * IN_W;                        \
            asm volatile("cp.async.cg.shared.global [%0], [%1], 16;"                \
                         :: "r"(sbp + hdst), "l"(src));                             \
        }                                                                           \
        asm volatile("cp.async.commit_group;");                                     \
    } while (0)

    LOAD_PH(0, 0);
    LOAD_PH(1, 1);

    const int rr = wid >> 1;             // warp's row within subtile (0..3)
    const int q  = (wid & 1) * 32;       // warp's 32-pos quarter
    float c[4][4];                       // [MMA j: pos block 8j][c-regs], persists kc pair
    int bi = 0;

    #pragma unroll 1
    for (int ph = 0; ph < 8; ph++) {
        if (ph < 7) asm volatile("cp.async.wait_group 1;");
        else        asm volatile("cp.async.wait_group 0;");
        __syncthreads();

        if (ph < 6) {
            int li = bi + 2; if (li >= 3) li -= 3;
            LOAD_PH(li, ph + 2);
        }

        const int kc = ph & 1;
        const uint32_t* Ab = stage + bi * BUFW;

        if (kc == 0) {
            #pragma unroll
            for (int j = 0; j < 4; j++)
                #pragma unroll
                for (int e = 0; e < 4; e++) c[j][e] = 0.f;
        }

        #pragma unroll
        for (int ky = 0; ky < 3; ky++) {
            // hoist 3 weight A-fragments for this (kc,ky)
            const uint4* wf = (const uint4*)(Wf + (kc * 9 + ky * 3) * 128) + lane;
            uint4 A0 = wf[0];
            uint4 A1 = wf[32];
            uint4 A2 = wf[64];
            // input B base: k-plane = lk (+4), row rr+ky, pos q + lm' (lm = n col)
            const uint32_t* bp = Ab + lk * PLANE + (rr + ky) * PITCH + q + lm;
            #pragma unroll
            for (int kx = 0; kx < 3; kx++) {
                const uint32_t* bb = bp + kx;
                uint32_t b0[4], b1[4];
                #pragma unroll
                for (int j = 0; j < 4; j++) {
                    b0[j] = bb[8 * j];
                    b1[j] = bb[8 * j + 4 * PLANE];
                }
                uint4 Ax = (kx == 0) ? A0 : (kx == 1) ? A1 : A2;
                #pragma unroll
                for (int j = 0; j < 4; j++)
                    mma_tf32(c[j], Ax.x, Ax.y, Ax.z, Ax.w, b0[j], b1[j]);
            }
        }

        if (kc == 1) {
            const int yo = Y0 + 4 * (ph >> 1) + rr;
            if (yo < OUT_W) {
                float b0f = bsm[lm] - 0.7f;
                float b1f = bsm[lm + 8] - 0.7f;
                float* y0 = y + ((size_t)n * 16 + lm) * OUT_HW + (size_t)yo * OUT_W;
                float* y1 = y0 + 8 * OUT_HW;
                #pragma unroll
                for (int j = 0; j < 4; j++) {
                    int xo = X0 + q + 8 * j + 2 * lk;   // even; pair fully in/out
                    if (xo < OUT_W) {
                        float2 v0, v1;
                        v0.x = mish_f(c[j][0] + b0f);
                        v0.y = mish_f(c[j][1] + b0f);
                        v1.x = mish_f(c[j][2] + b1f);
                        v1.y = mish_f(c[j][3] + b1f);
                        *(float2*)(y0 + xo) = v0;
                        *(float2*)(y1 + xo) = v1;
                    }
                }
            }
        }

        bi = (bi == 2) ? 0 : bi + 1;
    }
}

extern "C" void kernel_launch(void* const* d_in, const int* in_sizes, int n_in,
                              void* d_out, int out_size)
{
    const float* x  = (const float*)d_in[0];
    const float* w  = (const float*)d_in[1];
    const float* b  = (const float*)d_in[2];
    float* y = (float*)d_out;

    cudaFuncSetAttribute(conv_tc_kernel,
                         cudaFuncAttributeMaxDynamicSharedMemorySize, SMEM_BYTES);

    int N = in_sizes[0] / (16 * IN_HW);                 // 32
    dim3 grid(4, 16, N);                                // 2048 CTAs
    conv_tc_kernel<<<grid, 256, SMEM_BYTES>>>(x, w, b, y);
}